// round 15
// baseline (speedup 1.0000x reference)
#include <cuda_runtime.h>
#include <cuda_fp16.h>

// MemoryNet attention: q,k,v (4, 1024, 2048) fp32 channels-first, 8 heads, d_head=128.
// Pass 1: convert K,V -> fp16 device-global buffers (once).
// Pass 2: fp16 HMMA flash-attention; cp.async staging; ldmatrix both GEMMs;
//         packed f16x2 exp (half the MUFU ops); l computed by ones-MMA on tensor pipe.
#define LL   2048
#define DH   128
#define BQ   128
#define BK   64
#define NKT  32
#define NT   256           // 8 warps, each owns 16 q-rows
#define TOTE (4 * 1024 * 2048)   // elements per tensor
#define ONES2 0x3C003C00u        // (1.0h, 1.0h)

static __device__ __half g_k16[TOTE];
static __device__ __half g_v16[TOTE];

// smem layout in HALF units
#define KS_STR 72          // K [128 d][64 key]  (144B rows: 16B-aligned, LDSM conflict-free)
#define VS_STR 72          // V [128 dv][64 ki]
#define KS_OFF 0
#define KS_SZ  (128 * KS_STR)            // 9216 per buffer, x2
#define VS_OFF (2 * KS_SZ)               // 18432
#define VS_SZ  (128 * VS_STR)            // 9216 per buffer, x2
#define SMEM_HALVES (VS_OFF + 2 * VS_SZ) // 36864
#define SMEM_BYTES  (SMEM_HALVES * 2)    // 73728 B
#define OUT_STRIDE 132                   // epilogue float buffer [128 d][128 q]

static __device__ __forceinline__ void mma16(float c[4], unsigned a0, unsigned a1,
                                             unsigned a2, unsigned a3,
                                             unsigned b0, unsigned b1) {
    asm volatile(
        "mma.sync.aligned.m16n8k16.row.col.f32.f16.f16.f32 "
        "{%0,%1,%2,%3}, {%4,%5,%6,%7}, {%8,%9}, {%0,%1,%2,%3};"
        : "+f"(c[0]), "+f"(c[1]), "+f"(c[2]), "+f"(c[3])
        : "r"(a0), "r"(a1), "r"(a2), "r"(a3), "r"(b0), "r"(b1));
}
static __device__ __forceinline__ void ldsm4(unsigned b[4], unsigned addr) {
    asm volatile("ldmatrix.sync.aligned.m8n8.x4.shared.b16 {%0,%1,%2,%3}, [%4];"
                 : "=r"(b[0]), "=r"(b[1]), "=r"(b[2]), "=r"(b[3]) : "r"(addr));
}
static __device__ __forceinline__ void ldsm4t(unsigned b[4], unsigned addr) {
    asm volatile("ldmatrix.sync.aligned.m8n8.x4.trans.shared.b16 {%0,%1,%2,%3}, [%4];"
                 : "=r"(b[0]), "=r"(b[1]), "=r"(b[2]), "=r"(b[3]) : "r"(addr));
}
static __device__ __forceinline__ unsigned packh2(float lo, float hi) {
    unsigned r;
    asm("cvt.rn.f16x2.f32 %0, %1, %2;" : "=r"(r) : "f"(hi), "f"(lo));
    return r;
}
static __device__ __forceinline__ unsigned h2ex2(unsigned x) {   // packed 2^x on both halves
    unsigned r;
    asm("ex2.approx.f16x2 %0, %1;" : "=r"(r) : "r"(x));
    return r;
}
static __device__ __forceinline__ void cpa16(unsigned dst, const void* src) {
    asm volatile("cp.async.cg.shared.global [%0], [%1], 16;" :: "r"(dst), "l"(src));
}
static __device__ __forceinline__ void cpa_commit() {
    asm volatile("cp.async.commit_group;");
}
static __device__ __forceinline__ void cpa_wait0() {
    asm volatile("cp.async.wait_group 0;");
}

// ---- Pass 1: fp32 -> fp16 conversion of K and V ----
__global__ __launch_bounds__(256)
void convert_kernel(const float* __restrict__ k, const float* __restrict__ v) {
    const int i = blockIdx.x * 256 + threadIdx.x;      // float4 index, TOTE/4 total
    float4 a = ((const float4*)k)[i];
    __half2 ha[2] = { __floats2half2_rn(a.x, a.y), __floats2half2_rn(a.z, a.w) };
    *(uint2*)(g_k16 + 4 * (size_t)i) = *(uint2*)ha;
    float4 b = ((const float4*)v)[i];
    __half2 hb[2] = { __floats2half2_rn(b.x, b.y), __floats2half2_rn(b.z, b.w) };
    *(uint2*)(g_v16 + 4 * (size_t)i) = *(uint2*)hb;
}

// ---- Pass 2: attention ----
__global__ __launch_bounds__(NT, 1)
void attn_kernel(const float* __restrict__ qg, const float* __restrict__ gamma,
                 float* __restrict__ out)
{
    extern __shared__ __half sm[];
    const unsigned sbu = (unsigned)__cvta_generic_to_shared(sm);

    const int tid  = threadIdx.x;
    const int w    = tid >> 5;
    const int lane = tid & 31;
    const int g    = lane >> 2;
    const int tg   = lane & 3;
    const int qb   = w << 4;      // warp's q base (8 warps x 16 = 128)

    const int qt = blockIdx.x;              // 0..15
    const int bh = blockIdx.y;              // 0..31
    const size_t base = (size_t)bh * ((size_t)DH * LL);
    const float*  qp = qg + base;
    const __half* kp = g_k16 + base;
    const __half* vp = g_v16 + base;
    const int q0 = qt * BQ;
    // fold log2(e) into the 1/sqrt(d) scale: softmax exp -> single packed EX2
    const float scale = 1.4426950408889634f * 0.08838834764831845f;

    // LDSM lane constants:
    const unsigned kRowBase = (unsigned)((lane & 15) * KS_STR + 8 * ((lane >> 4) & 1));
    const unsigned vRowBase = (unsigned)((8 * ((lane >> 4) & 1) + (lane & 7)) * VS_STR
                                         + 8 * ((lane >> 3) & 1));

    // ---- preload Q fragments into registers (scaled; once per kernel) ----
    unsigned qf[8][4];
    #pragma unroll
    for (int kk = 0; kk < 8; kk++) {
        const float* c0 = qp + (size_t)(16 * kk + 2 * tg) * LL + q0 + qb + g;
        const float* c1 = c0 + 8 * (size_t)LL;
        qf[kk][0] = packh2(c0[0] * scale, c0[LL] * scale);
        qf[kk][1] = packh2(c0[8] * scale, c0[LL + 8] * scale);
        qf[kk][2] = packh2(c1[0] * scale, c1[LL] * scale);
        qf[kk][3] = packh2(c1[8] * scale, c1[LL + 8] * scale);
    }

    // ---- prologue: cp.async tile 0 into buffer 0 ----
    #pragma unroll
    for (int i = 0; i < 4; i++) {
        const int idx = tid + 256 * i;
        const int row = idx >> 3;
        const int c8  = (idx & 7) * 8;
        cpa16(sbu + 2 * (unsigned)(KS_OFF + row * KS_STR + c8), kp + (size_t)row * LL + c8);
        cpa16(sbu + 2 * (unsigned)(VS_OFF + row * VS_STR + c8), vp + (size_t)row * LL + c8);
    }
    cpa_commit();

    float o[16][4];
    #pragma unroll
    for (int nt = 0; nt < 16; nt++)
        #pragma unroll
        for (int i = 0; i < 4; i++) o[nt][i] = 0.0f;

    float lacc[4] = {0.f, 0.f, 0.f, 0.f};   // l via ones-MMA: lacc[0]=l(row g), lacc[2]=l(row g+8)

    cpa_wait0();

    for (int t = 0; t < NKT; t++) {
        const unsigned kbu = sbu + 2 * (unsigned)(KS_OFF + (t & 1) * KS_SZ);
        const unsigned vbu = sbu + 2 * (unsigned)(VS_OFF + (t & 1) * VS_SZ);
        const bool pf = (t + 1 < NKT);

        __syncthreads();   // tile t visible CTA-wide; buffers (t+1)&1 free

        // ---- issue cp.async for tile t+1 (into the other buffers) ----
        if (pf) {
            const int kn = (t + 1) * BK;
            const unsigned kbo = 2 * (unsigned)(KS_OFF + ((t + 1) & 1) * KS_SZ);
            const unsigned vbo = 2 * (unsigned)(VS_OFF + ((t + 1) & 1) * VS_SZ);
            #pragma unroll
            for (int i = 0; i < 4; i++) {
                const int idx = tid + 256 * i;
                const int row = idx >> 3;
                const int c8  = (idx & 7) * 8;
                cpa16(sbu + kbo + 2 * (unsigned)(row * KS_STR + c8),
                      kp + (size_t)row * LL + kn + c8);
                cpa16(sbu + vbo + 2 * (unsigned)(row * VS_STR + c8),
                      vp + (size_t)row * LL + kn + c8);
            }
            cpa_commit();
        }

        // ---- fused GEMM1 -> packed exp -> GEMM2, per n-block p ----
        #pragma unroll
        for (int p = 0; p < 4; p++) {
            // GEMM1 slice: S n-tiles 2p, 2p+1 over full d (k = 128)
            float s0[4] = {0.f, 0.f, 0.f, 0.f};
            float s1[4] = {0.f, 0.f, 0.f, 0.f};
            #pragma unroll
            for (int kk = 0; kk < 8; kk++) {
                unsigned b[4];
                ldsm4t(b, kbu + 2 * (kRowBase + (unsigned)(16 * kk) * KS_STR
                                     + (unsigned)(16 * p)));
                mma16(s0, qf[kk][0], qf[kk][1], qf[kk][2], qf[kk][3], b[0], b[1]);
                mma16(s1, qf[kk][0], qf[kk][1], qf[kk][2], qf[kk][3], b[2], b[3]);
            }
            // packed exp (fixed max): A-fragment = 2^(f16x2 S)
            const unsigned a0 = h2ex2(packh2(s0[0], s0[1]));
            const unsigned a1 = h2ex2(packh2(s0[2], s0[3]));
            const unsigned a2 = h2ex2(packh2(s1[0], s1[1]));
            const unsigned a3 = h2ex2(packh2(s1[2], s1[3]));
            // l row-sums on the tensor pipe: C += P . ones
            mma16(lacc, a0, a1, a2, a3, ONES2, ONES2);
            // GEMM2 partial k-step p: O[16q][128d] += P[:, 16p:16p+16] . V-slice
            #pragma unroll
            for (int pp = 0; pp < 8; pp++) {
                unsigned bv[4];
                ldsm4(bv, vbu + 2 * (vRowBase + (unsigned)(16 * p)
                                     + (unsigned)(16 * pp) * VS_STR));
                mma16(o[2*pp    ], a0, a1, a2, a3, bv[0], bv[1]);
                mma16(o[2*pp + 1], a0, a1, a2, a3, bv[2], bv[3]);
            }
        }

        cpa_wait0();   // tile t+1 landed (this thread's chunks); barrier publishes CTA-wide
    }

    // ---- epilogue: l already complete per-thread (ones-MMA); O/l * gamma ----
    const float gm = *gamma;
    const float inv0 = gm / lacc[0];   // row g
    const float inv1 = gm / lacc[2];   // row g+8

    __syncthreads();
    float* sOut = (float*)sm;        // [128 d][128 q] floats, stride OUT_STRIDE
    #pragma unroll
    for (int nt = 0; nt < 16; nt++) {
        const int d0 = 8 * nt + 2 * tg;
        sOut[(d0    ) * OUT_STRIDE + qb + g    ] = o[nt][0] * inv0;
        sOut[(d0 + 1) * OUT_STRIDE + qb + g    ] = o[nt][1] * inv0;
        sOut[(d0    ) * OUT_STRIDE + qb + g + 8] = o[nt][2] * inv1;
        sOut[(d0 + 1) * OUT_STRIDE + qb + g + 8] = o[nt][3] * inv1;
    }
    __syncthreads();

    #pragma unroll
    for (int it = 0; it < 16; it++) {
        const int idx = tid + NT * it;     // 4096 float4s = 128 d x 32 q-quads
        const int d  = idx >> 5;
        const int qv = idx & 31;
        float4 tt = *(const float4*)(sOut + d * OUT_STRIDE + 4 * qv);
        *(float4*)(out + base + (size_t)d * LL + q0 + 4 * qv) = tt;
    }
}

extern "C" void kernel_launch(void* const* d_in, const int* in_sizes, int n_in,
                              void* d_out, int out_size)
{
    const float* q     = (const float*)d_in[0];
    const float* k     = (const float*)d_in[1];
    const float* v     = (const float*)d_in[2];
    const float* gamma = (const float*)d_in[3];
    float* out = (float*)d_out;

    cudaFuncSetAttribute(attn_kernel, cudaFuncAttributeMaxDynamicSharedMemorySize, SMEM_BYTES);

    convert_kernel<<<TOTE / 4 / 256, 256>>>(k, v);      // 2048 blocks
    dim3 grid(LL / BQ, 32);    // 16 q-tiles x 32 (b,h) = 512 CTAs
    attn_kernel<<<grid, NT, SMEM_BYTES>>>(q, gamma, out);
}

// round 16
// speedup vs baseline: 1.1452x; 1.1452x over previous
#include <cuda_runtime.h>
#include <cuda_fp16.h>

// MemoryNet attention: q,k,v (4, 1024, 2048) fp32 channels-first, 8 heads, d_head=128.
// Pass 1: convert K,V -> fp16 device-global buffers (once).
// Pass 2: fp16 HMMA flash-attention; cp.async staging; ldmatrix both GEMMs;
//         BQ=64 / 128 threads / 2 CTAs per SM for phase-decorrelated overlap.
#define LL   2048
#define DH   128
#define BQ   64
#define BK   64
#define NKT  32
#define NT   128           // 4 warps, each owns 16 q-rows
#define TOTE (4 * 1024 * 2048)   // elements per tensor

static __device__ __half g_k16[TOTE];
static __device__ __half g_v16[TOTE];

// smem layout in HALF units
#define KS_STR 72          // K [128 d][64 key]  (144B rows: 16B-aligned, LDSM conflict-free)
#define VS_STR 72          // V [128 dv][64 ki]
#define KS_OFF 0
#define KS_SZ  (128 * KS_STR)            // 9216 per buffer, x2
#define VS_OFF (2 * KS_SZ)               // 18432
#define VS_SZ  (128 * VS_STR)            // 9216 per buffer, x2
#define SMEM_HALVES (VS_OFF + 2 * VS_SZ) // 36864
#define SMEM_BYTES  (SMEM_HALVES * 2)    // 73728 B -> 2 CTAs/SM (147456 <= 228KB)
#define OUT_STRIDE 68                    // epilogue float buffer [128 d][64 q]

static __device__ __forceinline__ void mma16(float c[4], unsigned a0, unsigned a1,
                                             unsigned a2, unsigned a3,
                                             unsigned b0, unsigned b1) {
    asm volatile(
        "mma.sync.aligned.m16n8k16.row.col.f32.f16.f16.f32 "
        "{%0,%1,%2,%3}, {%4,%5,%6,%7}, {%8,%9}, {%0,%1,%2,%3};"
        : "+f"(c[0]), "+f"(c[1]), "+f"(c[2]), "+f"(c[3])
        : "r"(a0), "r"(a1), "r"(a2), "r"(a3), "r"(b0), "r"(b1));
}
static __device__ __forceinline__ void ldsm4(unsigned b[4], unsigned addr) {
    asm volatile("ldmatrix.sync.aligned.m8n8.x4.shared.b16 {%0,%1,%2,%3}, [%4];"
                 : "=r"(b[0]), "=r"(b[1]), "=r"(b[2]), "=r"(b[3]) : "r"(addr));
}
static __device__ __forceinline__ void ldsm4t(unsigned b[4], unsigned addr) {
    asm volatile("ldmatrix.sync.aligned.m8n8.x4.trans.shared.b16 {%0,%1,%2,%3}, [%4];"
                 : "=r"(b[0]), "=r"(b[1]), "=r"(b[2]), "=r"(b[3]) : "r"(addr));
}
static __device__ __forceinline__ unsigned packh2(float lo, float hi) {
    unsigned r;
    asm("cvt.rn.f16x2.f32 %0, %1, %2;" : "=r"(r) : "f"(hi), "f"(lo));
    return r;
}
static __device__ __forceinline__ float ex2(float x) {
    float r;
    asm("ex2.approx.ftz.f32 %0, %1;" : "=f"(r) : "f"(x));
    return r;
}
static __device__ __forceinline__ void cpa16(unsigned dst, const void* src) {
    asm volatile("cp.async.cg.shared.global [%0], [%1], 16;" :: "r"(dst), "l"(src));
}
static __device__ __forceinline__ void cpa_commit() {
    asm volatile("cp.async.commit_group;");
}
static __device__ __forceinline__ void cpa_wait0() {
    asm volatile("cp.async.wait_group 0;");
}

// ---- Pass 1: fp32 -> fp16 conversion of K and V ----
__global__ __launch_bounds__(256)
void convert_kernel(const float* __restrict__ k, const float* __restrict__ v) {
    const int i = blockIdx.x * 256 + threadIdx.x;      // float4 index, TOTE/4 total
    float4 a = ((const float4*)k)[i];
    __half2 ha[2] = { __floats2half2_rn(a.x, a.y), __floats2half2_rn(a.z, a.w) };
    *(uint2*)(g_k16 + 4 * (size_t)i) = *(uint2*)ha;
    float4 b = ((const float4*)v)[i];
    __half2 hb[2] = { __floats2half2_rn(b.x, b.y), __floats2half2_rn(b.z, b.w) };
    *(uint2*)(g_v16 + 4 * (size_t)i) = *(uint2*)hb;
}

// ---- Pass 2: attention ----
__global__ __launch_bounds__(NT, 2)
void attn_kernel(const float* __restrict__ qg, const float* __restrict__ gamma,
                 float* __restrict__ out)
{
    extern __shared__ __half sm[];
    const unsigned sbu = (unsigned)__cvta_generic_to_shared(sm);

    const int tid  = threadIdx.x;
    const int w    = tid >> 5;
    const int lane = tid & 31;
    const int g    = lane >> 2;
    const int tg   = lane & 3;
    const int qb   = w << 4;      // warp's q base (4 warps x 16 = 64)

    const int qt = blockIdx.x;              // 0..31
    const int bh = blockIdx.y;              // 0..31
    const size_t base = (size_t)bh * ((size_t)DH * LL);
    const float*  qp = qg + base;
    const __half* kp = g_k16 + base;
    const __half* vp = g_v16 + base;
    const int q0 = qt * BQ;
    // fold log2(e) into the 1/sqrt(d) scale: softmax exp -> single EX2
    const float scale = 1.4426950408889634f * 0.08838834764831845f;

    // LDSM lane constants:
    const unsigned kRowBase = (unsigned)((lane & 15) * KS_STR + 8 * ((lane >> 4) & 1));
    const unsigned vRowBase = (unsigned)((8 * ((lane >> 4) & 1) + (lane & 7)) * VS_STR
                                         + 8 * ((lane >> 3) & 1));

    // ---- preload Q fragments into registers (scaled; once per kernel) ----
    unsigned qf[8][4];
    #pragma unroll
    for (int kk = 0; kk < 8; kk++) {
        const float* c0 = qp + (size_t)(16 * kk + 2 * tg) * LL + q0 + qb + g;
        const float* c1 = c0 + 8 * (size_t)LL;
        qf[kk][0] = packh2(c0[0] * scale, c0[LL] * scale);
        qf[kk][1] = packh2(c0[8] * scale, c0[LL + 8] * scale);
        qf[kk][2] = packh2(c1[0] * scale, c1[LL] * scale);
        qf[kk][3] = packh2(c1[8] * scale, c1[LL + 8] * scale);
    }

    // ---- prologue: cp.async tile 0 into buffer 0 (128 threads, 8 chunks each per tensor) ----
    #pragma unroll
    for (int i = 0; i < 8; i++) {
        const int idx = tid + NT * i;       // 1024 chunks per tensor tile
        const int row = idx >> 3;
        const int c8  = (idx & 7) * 8;
        cpa16(sbu + 2 * (unsigned)(KS_OFF + row * KS_STR + c8), kp + (size_t)row * LL + c8);
        cpa16(sbu + 2 * (unsigned)(VS_OFF + row * VS_STR + c8), vp + (size_t)row * LL + c8);
    }
    cpa_commit();

    float o[16][4];
    #pragma unroll
    for (int nt = 0; nt < 16; nt++)
        #pragma unroll
        for (int i = 0; i < 4; i++) o[nt][i] = 0.0f;

    float l0 = 0.0f, l1 = 0.0f;   // per-thread partial denominators

    cpa_wait0();

    for (int t = 0; t < NKT; t++) {
        const unsigned kbu = sbu + 2 * (unsigned)(KS_OFF + (t & 1) * KS_SZ);
        const unsigned vbu = sbu + 2 * (unsigned)(VS_OFF + (t & 1) * VS_SZ);
        const bool pf = (t + 1 < NKT);

        __syncthreads();   // tile t visible CTA-wide; buffers (t+1)&1 free

        // ---- issue cp.async for tile t+1 (into the other buffers) ----
        if (pf) {
            const int kn = (t + 1) * BK;
            const unsigned kbo = 2 * (unsigned)(KS_OFF + ((t + 1) & 1) * KS_SZ);
            const unsigned vbo = 2 * (unsigned)(VS_OFF + ((t + 1) & 1) * VS_SZ);
            #pragma unroll
            for (int i = 0; i < 8; i++) {
                const int idx = tid + NT * i;
                const int row = idx >> 3;
                const int c8  = (idx & 7) * 8;
                cpa16(sbu + kbo + 2 * (unsigned)(row * KS_STR + c8),
                      kp + (size_t)row * LL + kn + c8);
                cpa16(sbu + vbo + 2 * (unsigned)(row * VS_STR + c8),
                      vp + (size_t)row * LL + kn + c8);
            }
            cpa_commit();
        }

        // ---- fused GEMM1 -> exp -> GEMM2, per n-block p ----
        #pragma unroll
        for (int p = 0; p < 4; p++) {
            // GEMM1 slice: S n-tiles 2p, 2p+1 over full d (k = 128)
            float s0[4] = {0.f, 0.f, 0.f, 0.f};
            float s1[4] = {0.f, 0.f, 0.f, 0.f};
            #pragma unroll
            for (int kk = 0; kk < 8; kk++) {
                unsigned b[4];
                ldsm4t(b, kbu + 2 * (kRowBase + (unsigned)(16 * kk) * KS_STR
                                     + (unsigned)(16 * p)));
                mma16(s0, qf[kk][0], qf[kk][1], qf[kk][2], qf[kk][3], b[0], b[1]);
                mma16(s1, qf[kk][0], qf[kk][1], qf[kk][2], qf[kk][3], b[2], b[3]);
            }
            // element-wise exp (fixed max): p = 2^s
            const float p00 = ex2(s0[0]);
            const float p01 = ex2(s0[1]);
            const float p10 = ex2(s0[2]);
            const float p11 = ex2(s0[3]);
            const float p20 = ex2(s1[0]);
            const float p21 = ex2(s1[1]);
            const float p30 = ex2(s1[2]);
            const float p31 = ex2(s1[3]);
            l0 += (p00 + p01) + (p20 + p21);
            l1 += (p10 + p11) + (p30 + p31);
            const unsigned a0 = packh2(p00, p01);
            const unsigned a1 = packh2(p10, p11);
            const unsigned a2 = packh2(p20, p21);
            const unsigned a3 = packh2(p30, p31);
            // GEMM2 partial k-step p: O[16q][128d] += P[:, 16p:16p+16] . V-slice
            #pragma unroll
            for (int pp = 0; pp < 8; pp++) {
                unsigned bv[4];
                ldsm4(bv, vbu + 2 * (vRowBase + (unsigned)(16 * p)
                                     + (unsigned)(16 * pp) * VS_STR));
                mma16(o[2*pp    ], a0, a1, a2, a3, bv[0], bv[1]);
                mma16(o[2*pp + 1], a0, a1, a2, a3, bv[2], bv[3]);
            }
        }

        cpa_wait0();   // tile t+1 landed (this thread's chunks); barrier publishes CTA-wide
    }

    // ---- epilogue: reduce l over the 4-lane group, then O/l * gamma ----
    l0 += __shfl_xor_sync(0xffffffffu, l0, 1);
    l0 += __shfl_xor_sync(0xffffffffu, l0, 2);
    l1 += __shfl_xor_sync(0xffffffffu, l1, 1);
    l1 += __shfl_xor_sync(0xffffffffu, l1, 2);
    const float gm = *gamma;
    const float inv0 = gm / l0;
    const float inv1 = gm / l1;

    __syncthreads();
    float* sOut = (float*)sm;        // [128 d][64 q] floats, stride OUT_STRIDE (34816 B)
    #pragma unroll
    for (int nt = 0; nt < 16; nt++) {
        const int d0 = 8 * nt + 2 * tg;
        sOut[(d0    ) * OUT_STRIDE + qb + g    ] = o[nt][0] * inv0;
        sOut[(d0 + 1) * OUT_STRIDE + qb + g    ] = o[nt][1] * inv0;
        sOut[(d0    ) * OUT_STRIDE + qb + g + 8] = o[nt][2] * inv1;
        sOut[(d0 + 1) * OUT_STRIDE + qb + g + 8] = o[nt][3] * inv1;
    }
    __syncthreads();

    #pragma unroll
    for (int it = 0; it < 16; it++) {
        const int idx = tid + NT * it;     // 2048 float4s = 128 d x 16 q-quads
        const int d  = idx >> 4;
        const int qv = idx & 15;
        float4 tt = *(const float4*)(sOut + d * OUT_STRIDE + 4 * qv);
        *(float4*)(out + base + (size_t)d * LL + q0 + 4 * qv) = tt;
    }
}

extern "C" void kernel_launch(void* const* d_in, const int* in_sizes, int n_in,
                              void* d_out, int out_size)
{
    const float* q     = (const float*)d_in[0];
    const float* k     = (const float*)d_in[1];
    const float* v     = (const float*)d_in[2];
    const float* gamma = (const float*)d_in[3];
    float* out = (float*)d_out;

    cudaFuncSetAttribute(attn_kernel, cudaFuncAttributeMaxDynamicSharedMemorySize, SMEM_BYTES);

    convert_kernel<<<TOTE / 4 / 256, 256>>>(k, v);      // 2048 blocks
    dim3 grid(LL / BQ, 32);    // 32 q-tiles x 32 (b,h) = 1024 CTAs
    attn_kernel<<<grid, NT, SMEM_BYTES>>>(q, gamma, out);
}